// round 7
// baseline (speedup 1.0000x reference)
#include <cuda_runtime.h>
#include <cstdint>

#define B 4
#define N 32768
#define CH 4096          // chunk size for first-pass sort
#define TOP 2048         // exact top-K kept per batch
#define POST 512
#define NMS_TH 0.7f
#define M 1024           // mask window
#define W 16             // u64 words per mask row (M/64)
#define NBLK 32          // fused-kernel grid size

typedef unsigned long long u64;

// ---------------- scratch (device globals, no allocation) ----------------
__device__ __align__(16) u64 g_topk[B * 8 * TOP];
__device__ __align__(16) u64 g_key[B * TOP];
__device__ float g_x1[B * TOP], g_y1[B * TOP], g_x2[B * TOP], g_y2[B * TOP], g_area[B * TOP];
__device__ u64 g_maskT[B * W * M];                  // transposed: [b][word][row]
__device__ unsigned int g_barc[3];                  // monotonic grid-barrier counters

// ---------------- grid barrier (monotonic, replay-safe) ----------------
__device__ __forceinline__ void grid_bar(int p) {
    __syncthreads();
    if (threadIdx.x == 0) {
        __threadfence();
        unsigned my = atomicAdd(&g_barc[p], 1u);
        unsigned target = (my / NBLK + 1u) * NBLK;
        while (true) {
            unsigned cur = *((volatile unsigned int*)&g_barc[p]);
            if ((unsigned)(cur - target) < 0x80000000u) break;   // cur >= target, wrap-safe
            __nanosleep(32);
        }
        __threadfence();
    }
    __syncthreads();
}

// ---------------- bitonic helpers: 4 elements per thread ----------------
__device__ __forceinline__ u64 u64max(u64 a, u64 b) { return a > b ? a : b; }
__device__ __forceinline__ u64 u64min(u64 a, u64 b) { return a < b ? a : b; }

__device__ __forceinline__ void cexp(u64& a, u64& b, bool desc) {
    u64 mx = a > b ? a : b;
    u64 mn = a > b ? b : a;
    a = desc ? mx : mn;
    b = desc ? mn : mx;
}

__device__ __forceinline__ void stage_smem(u64* s, u64 v[4], int tid, int j, int k) {
    #pragma unroll
    for (int r = 0; r < 4; r++) s[(tid << 2) + r] = v[r];
    __syncthreads();
    #pragma unroll
    for (int r = 0; r < 4; r++) {
        int idx = (tid << 2) + r;
        u64 w = s[idx ^ j];
        bool keepmax = (((idx & j) == 0) == ((idx & k) == 0));
        v[r] = keepmax ? u64max(v[r], w) : u64min(v[r], w);
    }
    __syncthreads();
}

__device__ __forceinline__ void stage_shfl(u64 v[4], int tid, int j, int k) {
    #pragma unroll
    for (int r = 0; r < 4; r++) {
        int idx = (tid << 2) + r;
        u64 w = __shfl_xor_sync(0xffffffffu, v[r], j >> 2);
        bool keepmax = (((idx & j) == 0) == ((idx & k) == 0));
        v[r] = keepmax ? u64max(v[r], w) : u64min(v[r], w);
    }
}

__device__ __forceinline__ void bitonic_descend(u64* s, u64 v[4], int tid, int jstart, int k) {
    int j = jstart;
    for (; j >= 128; j >>= 1) stage_smem(s, v, tid, j, k);
    for (; j >= 4; j >>= 1) stage_shfl(v, tid, j, k);
    int idx = tid << 2;
    if (j == 2) {
        cexp(v[0], v[2], ((idx) & k) == 0);
        cexp(v[1], v[3], ((idx + 1) & k) == 0);
    }
    cexp(v[0], v[1], ((idx) & k) == 0);
    cexp(v[2], v[3], ((idx + 2) & k) == 0);
}

__device__ __forceinline__ u64 make_key(float c0, float c1, float c2, int n) {
    float best = c0; int lab = 0;
    if (c1 > best) { best = c1; lab = 1; }
    if (c2 > best) { best = c2; lab = 2; }
    return ((u64)__float_as_uint(best) << 32) | ((u64)(0x7FFFu - (unsigned)n) << 2) | (u64)lab;
}

// top-TOP of two desc-sorted TOP-lists; out[k] = (k+1)-th largest. Keys are distinct.
__device__ __forceinline__ u64 merge_pick(const u64* __restrict__ pa,
                                          const u64* __restrict__ pb, int k) {
    int lo = (k + 1 > TOP) ? (k + 1 - TOP) : 0;
    int hi = (k + 1 < TOP) ? (k + 1) : TOP;
    while (lo < hi) {
        int mid = (lo + hi) >> 1;
        if (pa[mid] > pb[k - mid]) lo = mid + 1;
        else hi = mid;
    }
    int cA = lo;
    u64 av = (cA > 0) ? pa[cA - 1] : ~0ull;
    u64 bv = (cA <= k) ? pb[k - cA] : ~0ull;
    return av < bv ? av : bv;
}

// ---------------- fused kernel: sort -> merge -> mask -> scan/emit ----------------
__global__ void __launch_bounds__(1024) k_fused(const float* __restrict__ cls,
                                                const float* __restrict__ boxes,
                                                float* __restrict__ out) {
    extern __shared__ char smem_raw[];
    int tid = threadIdx.x;
    int cta = blockIdx.x;

    // ================= phase A: fused score + chunk sort + keep top-2048 =========
    {
        u64* s = (u64*)smem_raw;
        int b = cta >> 3;
        int c = cta & 7;
        const float4* p = (const float4*)(cls + ((size_t)b * N + (size_t)c * CH) * 3);
        float4 f0 = p[3 * tid], f1 = p[3 * tid + 1], f2 = p[3 * tid + 2];
        int n0 = c * CH + (tid << 2);
        u64 v[4];
        v[0] = make_key(f0.x, f0.y, f0.z, n0);
        v[1] = make_key(f0.w, f1.x, f1.y, n0 + 1);
        v[2] = make_key(f1.z, f1.w, f2.x, n0 + 2);
        v[3] = make_key(f2.y, f2.z, f2.w, n0 + 3);
        #pragma unroll
        for (int k = 2; k <= CH; k <<= 1)
            bitonic_descend(s, v, tid, k >> 1, k);
        if (tid < TOP / 4) {
            u64* d = g_topk + ((size_t)(b * 8 + c)) * TOP + (tid << 2);
            *(ulonglong2*)(d)     = make_ulonglong2(v[0], v[1]);
            *(ulonglong2*)(d + 2) = make_ulonglong2(v[2], v[3]);
        }
    }
    grid_bar(0);

    // ================= phase B: 8-way merge-path tournament + gather/corners =====
    if (cta < B) {
        u64* wk = (u64*)smem_raw;   // 24576 u64 = 192 KB
        int b = cta;
        for (int idx = tid; idx < 8 * TOP; idx += 1024)
            wk[idx] = g_topk[(size_t)b * 8 * TOP + idx];
        __syncthreads();
        for (int e = tid; e < 4 * TOP; e += 1024) {
            int p = e >> 11, k = e & (TOP - 1);
            wk[16384 + p * TOP + k] = merge_pick(wk + p * 4096, wk + p * 4096 + TOP, k);
        }
        __syncthreads();
        for (int e = tid; e < 2 * TOP; e += 1024) {
            int q = e >> 11, k = e & (TOP - 1);
            wk[q * TOP + k] = merge_pick(wk + 16384 + q * 4096, wk + 16384 + q * 4096 + TOP, k);
        }
        __syncthreads();
        for (int e = tid; e < TOP; e += 1024)
            wk[16384 + e] = merge_pick(wk, wk + TOP, e);
        __syncthreads();
        for (int i = tid; i < TOP; i += 1024) {
            u64 key = wk[16384 + i];
            int o = b * TOP + i;
            g_key[o] = key;
            unsigned n = 0x7FFFu - (unsigned)((key >> 2) & 0x7FFF);
            const float* bx = boxes + ((size_t)b * N + n) * 7;
            float x = bx[0], y = bx[1], dx = bx[3], dy = bx[4];
            g_x1[o] = x - 0.5f * dx;
            g_x2[o] = x + 0.5f * dx;
            g_y1[o] = y - 0.5f * dy;
            g_y2[o] = y + 0.5f * dy;
            g_area[o] = dx * dy;
        }
    }
    grid_bar(1);

    // ================= phase C: suppression mask (transposed), 128 rows / CTA ====
    {
        float* rx1 = (float*)smem_raw;          // 128 each
        float* ry1 = rx1 + 128;
        float* rx2 = rx1 + 256;
        float* ry2 = rx1 + 384;
        float* ra  = rx1 + 512;
        float* cx1 = rx1 + 640;                 // 512 each
        float* cy1 = cx1 + 512;
        float* cx2 = cx1 + 1024;
        float* cy2 = cx1 + 1536;
        float* ca  = cx1 + 2048;
        int b = cta >> 3;
        int rowBase = (cta & 7) * 128;

        if (tid < 128) {
            int g = b * TOP + rowBase + tid;
            rx1[tid] = g_x1[g]; ry1[tid] = g_y1[g];
            rx2[tid] = g_x2[g]; ry2[tid] = g_y2[g];
            ra[tid] = g_area[g];
        }
        #pragma unroll
        for (int cc = 0; cc < 2; cc++) {
            __syncthreads();
            if (tid < 512) {
                int g = b * TOP + cc * 512 + tid;
                cx1[tid] = g_x1[g]; cy1[tid] = g_y1[g];
                cx2[tid] = g_x2[g]; cy2[tid] = g_y2[g];
                ca[tid] = g_area[g];
            }
            __syncthreads();
            int r = tid >> 3;
            int w = tid & 7;
            int row = rowBase + r;
            float x1 = rx1[r], y1 = ry1[r], x2 = rx2[r], y2 = ry2[r], ai = ra[r];
            u64 bits = 0;
            int cb = w * 64;
            int colBase = cc * 512 + cb;
            #pragma unroll 4
            for (int j = 0; j < 64; j++) {
                float ix = fminf(x2, cx2[cb + j]) - fmaxf(x1, cx1[cb + j]);
                float iy = fminf(y2, cy2[cb + j]) - fmaxf(y1, cy1[cb + j]);
                ix = fmaxf(ix, 0.f);
                iy = fmaxf(iy, 0.f);
                float inter = ix * iy;
                float iou = inter / (ai + ca[cb + j] - inter + 1e-6f);
                if ((colBase + j > row) & (iou > NMS_TH)) bits |= 1ull << j;
            }
            g_maskT[((size_t)b * W + (cc * 8 + w)) * M + row] = bits;
        }
    }
    grid_bar(2);

    // ================= phase D: fixpoint keep-vector + fallback + emit ===========
    if (cta >= B) return;
    {
        u64* sm = (u64*)smem_raw;               // 16384 u64 = 128 KB
        __shared__ u64 kw[W];
        __shared__ u64 partial[32];
        __shared__ int s_keep[POST];
        __shared__ int s_pfx[W + 1];
        __shared__ int s_changed, s_conv, s_kept, s_fail, s_i;
        int b = cta;

        for (int idx = tid; idx < M * W; idx += 1024)
            sm[idx] = g_maskT[(size_t)b * M * W + idx];
        if (tid < W) kw[tid] = ~0ull;
        if (tid == 0) { s_changed = 0; s_conv = 0; s_fail = 0; }
        __syncthreads();

        int w = tid >> 6;
        int t = tid & 63;
        const u64* mrow = sm + w * M;

        for (int iter = 0; iter < 64; iter++) {
            u64 acc = 0;
            #pragma unroll
            for (int s = 0; s < W; s++) {
                u64 kws = kw[s];
                if ((kws >> t) & 1ull) acc |= mrow[(s << 6) | t];
            }
            #pragma unroll
            for (int d = 16; d >= 1; d >>= 1) acc |= __shfl_xor_sync(0xffffffffu, acc, d);
            if ((tid & 31) == 0) partial[tid >> 5] = acc;
            __syncthreads();
            if (tid < W) {
                u64 sup = partial[2 * tid] | partial[2 * tid + 1];
                u64 nk = ~sup;
                if (nk != kw[tid]) { kw[tid] = nk; s_changed = 1; }
            }
            __syncthreads();
            bool stop = (s_changed == 0);
            __syncthreads();
            if (stop) { if (tid == 0) s_conv = 1; break; }
            if (tid == 0) s_changed = 0;
            __syncthreads();
        }
        __syncthreads();

        if (tid == 0) {
            if (!s_conv) { s_fail = 1; }
            else {
                int tot = 0;
                s_pfx[0] = 0;
                #pragma unroll
                for (int q = 0; q < W; q++) { tot += __popcll(kw[q]); s_pfx[q + 1] = tot; }
                s_fail = (tot < POST) ? 1 : 0;
                s_kept = POST;
            }
        }
        __syncthreads();

        if (!s_fail) {
            if (tid < W) {
                int pos = s_pfx[tid];
                u64 kk = kw[tid];
                for (int bit = 0; bit < 64 && pos < POST; bit++) {
                    if ((kk >> bit) & 1ull) { s_keep[pos] = (tid << 6) + bit; pos++; }
                }
            }
            __syncthreads();
        } else {
            // sequential greedy fallback over all TOP candidates (safety path)
            float* fx1 = (float*)sm;
            float* fy1 = fx1 + TOP;
            float* fx2 = fx1 + 2 * TOP;
            float* fy2 = fx1 + 3 * TOP;
            float* fa  = fx1 + 4 * TOP;
            unsigned char* sup = (unsigned char*)(fx1 + 5 * TOP);
            __syncthreads();
            for (int i = tid; i < TOP; i += 1024) {
                int o = b * TOP + i;
                fx1[i] = g_x1[o]; fy1[i] = g_y1[o];
                fx2[i] = g_x2[o]; fy2[i] = g_y2[o];
                fa[i] = g_area[o];
                sup[i] = 0;
            }
            __syncthreads();
            int kept = 0, cursor = 0;
            while (true) {
                if (tid == 0) {
                    int i = cursor;
                    while (i < TOP && sup[i]) i++;
                    s_i = (i < TOP) ? i : -1;
                }
                __syncthreads();
                int i = s_i;
                if (i < 0) break;
                cursor = i + 1;
                if (tid == 0) s_keep[kept] = i;
                kept++;
                if (kept >= POST) break;
                float xi1 = fx1[i], yi1 = fy1[i], xi2 = fx2[i], yi2 = fy2[i], ai = fa[i];
                for (int j = i + 1 + tid; j < TOP; j += 1024) {
                    if (!sup[j]) {
                        float ix = fminf(xi2, fx2[j]) - fmaxf(xi1, fx1[j]);
                        float iy = fminf(yi2, fy2[j]) - fmaxf(yi1, fy1[j]);
                        ix = fmaxf(ix, 0.f);
                        iy = fmaxf(iy, 0.f);
                        float inter = ix * iy;
                        if (inter / (ai + fa[j] - inter + 1e-6f) > NMS_TH) sup[j] = 1;
                    }
                }
                __syncthreads();
            }
            if (tid == 0) s_kept = kept;
            __syncthreads();
        }

        int kept = s_kept;
        float* rois   = out;
        float* scores = out + B * POST * 7;
        float* labs   = out + B * POST * 7 + B * POST;
        for (int s = tid; s < POST; s += 1024) {
            int o = b * POST + s;
            if (s < kept) {
                u64 key = g_key[b * TOP + s_keep[s]];
                unsigned n = 0x7FFFu - (unsigned)((key >> 2) & 0x7FFF);
                const float* bx = boxes + ((size_t)b * N + n) * 7;
                #pragma unroll
                for (int q = 0; q < 7; q++) rois[o * 7 + q] = bx[q];
                scores[o] = __uint_as_float((unsigned)(key >> 32));
                labs[o] = (float)((key & 3ull) + 1);
            } else {
                #pragma unroll
                for (int q = 0; q < 7; q++) rois[o * 7 + q] = 0.f;
                scores[o] = 0.f;
                labs[o] = 0.f;
            }
        }
    }
}

// ---------------- launch ----------------
extern "C" void kernel_launch(void* const* d_in, const int* in_sizes, int n_in,
                              void* d_out, int out_size) {
    const float* boxes = (const float*)d_in[0];
    const float* cls   = (const float*)d_in[1];
    if (in_sizes[0] == B * N * 3) {
        cls = (const float*)d_in[0];
        boxes = (const float*)d_in[1];
    }

    cudaFuncSetAttribute(k_fused, cudaFuncAttributeMaxDynamicSharedMemorySize, 196608);
    k_fused<<<NBLK, 1024, 196608>>>(cls, boxes, (float*)d_out);
}

// round 8
// speedup vs baseline: 1.0883x; 1.0883x over previous
#include <cuda_runtime.h>
#include <cstdint>

#define B 4
#define N 32768
#define CH 4096
#define TOP 2048
#define POST 512
#define NMS_TH 0.7f
#define M 1024           // mask window
#define W 16             // u64 words per mask row
#define BINS 4096
#define CAND_CAP 4096

typedef unsigned long long u64;

// ---------------- scratch ----------------
__device__ __align__(16) u64 g_keysA[B * N];
__device__ unsigned g_hist_part[32 * BINS];
__device__ int g_thr[B];
__device__ unsigned g_cand_cnt[B];
__device__ int g_ovf[B];
__device__ __align__(16) u64 g_cand[B * CAND_CAP];
__device__ __align__(16) u64 g_key[B * TOP];
__device__ float g_x1[B * TOP], g_y1[B * TOP], g_x2[B * TOP], g_y2[B * TOP], g_area[B * TOP];
__device__ u64 g_maskT[B * W * M];

// ---------------- bitonic helpers (4 elems/thread, 4096 keys) ----------------
__device__ __forceinline__ u64 u64max(u64 a, u64 b) { return a > b ? a : b; }
__device__ __forceinline__ u64 u64min(u64 a, u64 b) { return a < b ? a : b; }

__device__ __forceinline__ void cexp(u64& a, u64& b, bool desc) {
    u64 mx = a > b ? a : b;
    u64 mn = a > b ? b : a;
    a = desc ? mx : mn;
    b = desc ? mn : mx;
}

__device__ __forceinline__ void stage_smem(u64* s, u64 v[4], int tid, int j, int k) {
    #pragma unroll
    for (int r = 0; r < 4; r++) s[(tid << 2) + r] = v[r];
    __syncthreads();
    #pragma unroll
    for (int r = 0; r < 4; r++) {
        int idx = (tid << 2) + r;
        u64 w = s[idx ^ j];
        bool keepmax = (((idx & j) == 0) == ((idx & k) == 0));
        v[r] = keepmax ? u64max(v[r], w) : u64min(v[r], w);
    }
    __syncthreads();
}

__device__ __forceinline__ void stage_shfl(u64 v[4], int tid, int j, int k) {
    #pragma unroll
    for (int r = 0; r < 4; r++) {
        int idx = (tid << 2) + r;
        u64 w = __shfl_xor_sync(0xffffffffu, v[r], j >> 2);
        bool keepmax = (((idx & j) == 0) == ((idx & k) == 0));
        v[r] = keepmax ? u64max(v[r], w) : u64min(v[r], w);
    }
}

__device__ __forceinline__ void bitonic_descend(u64* s, u64 v[4], int tid, int jstart, int k) {
    int j = jstart;
    for (; j >= 128; j >>= 1) stage_smem(s, v, tid, j, k);
    for (; j >= 4; j >>= 1) stage_shfl(v, tid, j, k);
    int idx = tid << 2;
    if (j == 2) {
        cexp(v[0], v[2], ((idx) & k) == 0);
        cexp(v[1], v[3], ((idx + 1) & k) == 0);
    }
    cexp(v[0], v[1], ((idx) & k) == 0);
    cexp(v[2], v[3], ((idx + 2) & k) == 0);
}

__device__ __forceinline__ void sort4096(u64* s, u64 v[4], int tid) {
    #pragma unroll
    for (int k = 2; k <= 4096; k <<= 1)
        bitonic_descend(s, v, tid, k >> 1, k);
}

__device__ __forceinline__ u64 make_key(float c0, float c1, float c2, int n) {
    float best = c0; int lab = 0;
    if (c1 > best) { best = c1; lab = 1; }
    if (c2 > best) { best = c2; lab = 2; }
    return ((u64)__float_as_uint(best) << 32) | ((u64)(0x7FFFu - (unsigned)n) << 2) | (u64)lab;
}

__device__ __forceinline__ int key_bin(u64 key) { return (int)((key >> 51) & 0xFFF); }

// top-TOP of two desc-sorted TOP-lists
__device__ __forceinline__ u64 merge_pick(const u64* __restrict__ pa,
                                          const u64* __restrict__ pb, int k) {
    int lo = (k + 1 > TOP) ? (k + 1 - TOP) : 0;
    int hi = (k + 1 < TOP) ? (k + 1) : TOP;
    while (lo < hi) {
        int mid = (lo + hi) >> 1;
        if (pa[mid] > pb[k - mid]) lo = mid + 1;
        else hi = mid;
    }
    int cA = lo;
    u64 av = (cA > 0) ? pa[cA - 1] : ~0ull;
    u64 bv = (cA <= k) ? pb[k - cA] : ~0ull;
    return av < bv ? av : bv;
}

// ---------------- kernel 1: keys + per-chunk histogram ----------------
__global__ void __launch_bounds__(1024) k_hist(const float* __restrict__ cls) {
    __shared__ unsigned hist[BINS];
    int cta = blockIdx.x;              // 32
    int tid = threadIdx.x;
    for (int i = tid; i < BINS; i += 1024) hist[i] = 0;
    __syncthreads();
    int b = cta >> 3, c = cta & 7;
    const float4* p = (const float4*)(cls + ((size_t)b * N + (size_t)c * CH) * 3);
    float4 f0 = p[3 * tid], f1 = p[3 * tid + 1], f2 = p[3 * tid + 2];
    int n0 = c * CH + (tid << 2);
    u64 v0 = make_key(f0.x, f0.y, f0.z, n0);
    u64 v1 = make_key(f0.w, f1.x, f1.y, n0 + 1);
    u64 v2 = make_key(f1.z, f1.w, f2.x, n0 + 2);
    u64 v3 = make_key(f2.y, f2.z, f2.w, n0 + 3);
    u64* d = g_keysA + (size_t)b * N + c * CH + (tid << 2);
    *(ulonglong2*)(d)     = make_ulonglong2(v0, v1);
    *(ulonglong2*)(d + 2) = make_ulonglong2(v2, v3);
    atomicAdd(&hist[key_bin(v0)], 1u);
    atomicAdd(&hist[key_bin(v1)], 1u);
    atomicAdd(&hist[key_bin(v2)], 1u);
    atomicAdd(&hist[key_bin(v3)], 1u);
    __syncthreads();
    for (int i = tid; i < BINS; i += 1024) g_hist_part[cta * BINS + i] = hist[i];
}

// ---------------- kernel 2: per-batch threshold via suffix sum ----------------
__global__ void __launch_bounds__(1024) k_thresh() {
    __shared__ unsigned bufA[BINS], bufB[BINS];
    int b = blockIdx.x, tid = threadIdx.x;
    for (int i = tid; i < BINS; i += 1024) {
        unsigned tot = 0;
        #pragma unroll
        for (int c = 0; c < 8; c++) tot += g_hist_part[(b * 8 + c) * BINS + i];
        bufA[i] = tot;
    }
    __syncthreads();
    unsigned* src = bufA;
    unsigned* dst = bufB;
    for (int dd = 1; dd < BINS; dd <<= 1) {
        for (int i = tid; i < BINS; i += 1024)
            dst[i] = src[i] + ((i + dd < BINS) ? src[i + dd] : 0u);
        __syncthreads();
        unsigned* tmp = src; src = dst; dst = tmp;
    }
    for (int i = tid; i < BINS; i += 1024) {
        if (src[i] >= TOP && (i == BINS - 1 || src[i + 1] < TOP)) g_thr[b] = i;
    }
    if (tid == 0) { g_cand_cnt[b] = 0; g_ovf[b] = 0; }
}

// ---------------- kernel 3: compact candidates (warp-aggregated) ----------------
__global__ void __launch_bounds__(1024) k_compact() {
    int cta = blockIdx.x;              // 32
    int tid = threadIdx.x;
    int b = cta >> 3, c = cta & 7;
    int t = g_thr[b];
    const u64* src = g_keysA + (size_t)b * N + c * CH + (tid << 2);
    ulonglong2 p0 = *(const ulonglong2*)(src);
    ulonglong2 p1 = *(const ulonglong2*)(src + 2);
    u64 vv[4] = {p0.x, p0.y, p1.x, p1.y};
    int lane = tid & 31;
    #pragma unroll
    for (int r = 0; r < 4; r++) {
        bool sel = key_bin(vv[r]) >= t;
        unsigned m = __ballot_sync(0xffffffffu, sel);
        if (m == 0) continue;
        int leader = __ffs(m) - 1;
        unsigned base = 0;
        if (lane == leader) base = atomicAdd(&g_cand_cnt[b], (unsigned)__popc(m));
        base = __shfl_sync(0xffffffffu, base, leader);
        if (sel) {
            unsigned pos = base + __popc(m & ((1u << lane) - 1u));
            if (pos < CAND_CAP) g_cand[(size_t)b * CAND_CAP + pos] = vv[r];
            else g_ovf[b] = 1;
        }
    }
}

// ---------------- kernel 4: sort candidates, top-2048, gather corners ----------------
__global__ void __launch_bounds__(1024) k_sortsel(const float* __restrict__ boxes) {
    extern __shared__ u64 sdyn[];      // 8192 u64 = 64 KB: s[4096] | R[2048] | tmp[2048]
    u64* s = sdyn;
    u64* R = sdyn + 4096;
    u64* tmpb = sdyn + 6144;
    int b = blockIdx.x, tid = threadIdx.x;

    if (!g_ovf[b]) {
        unsigned cnt = g_cand_cnt[b];
        if (cnt > CAND_CAP) cnt = CAND_CAP;
        u64 v[4];
        #pragma unroll
        for (int r = 0; r < 4; r++) {
            unsigned i = (tid << 2) + r;
            v[r] = (i < cnt) ? g_cand[(size_t)b * CAND_CAP + i] : 0ull;
        }
        sort4096(s, v, tid);
        if (tid < TOP / 4) {
            #pragma unroll
            for (int r = 0; r < 4; r++) R[(tid << 2) + r] = v[r];
        }
        __syncthreads();
    } else {
        // robust path: sequential chunk sorts + running merge (pathological ties only)
        for (int c = 0; c < 8; c++) {
            u64 v[4];
            const u64* srcp = g_keysA + (size_t)b * N + c * CH + (tid << 2);
            ulonglong2 p0 = *(const ulonglong2*)(srcp);
            ulonglong2 p1 = *(const ulonglong2*)(srcp + 2);
            v[0] = p0.x; v[1] = p0.y; v[2] = p1.x; v[3] = p1.y;
            sort4096(s, v, tid);
            if (c == 0) {
                if (tid < TOP / 4) {
                    #pragma unroll
                    for (int r = 0; r < 4; r++) R[(tid << 2) + r] = v[r];
                }
                __syncthreads();
            } else {
                // stage chunk top-2048 into s[0..2048)
                if (tid < TOP / 4) {
                    #pragma unroll
                    for (int r = 0; r < 4; r++) s[(tid << 2) + r] = v[r];
                }
                __syncthreads();
                for (int k = tid; k < TOP; k += 1024) tmpb[k] = merge_pick(R, s, k);
                __syncthreads();
                for (int k = tid; k < TOP; k += 1024) R[k] = tmpb[k];
                __syncthreads();
            }
        }
    }

    // emit keys + corners from R
    for (int i = tid; i < TOP; i += 1024) {
        u64 key = R[i];
        int o = b * TOP + i;
        g_key[o] = key;
        unsigned n = 0x7FFFu - (unsigned)((key >> 2) & 0x7FFF);
        const float* bx = boxes + ((size_t)b * N + n) * 7;
        float x = bx[0], y = bx[1], dx = bx[3], dy = bx[4];
        g_x1[o] = x - 0.5f * dx;
        g_x2[o] = x + 0.5f * dx;
        g_y1[o] = y - 0.5f * dy;
        g_y2[o] = y + 0.5f * dy;
        g_area[o] = dx * dy;
    }
}

// ---------------- kernel 5: suppression mask (transposed), 128 rows/CTA ----------------
__global__ void __launch_bounds__(1024) k_mask() {
    __shared__ float rx1[128], ry1[128], rx2[128], ry2[128], ra[128];
    __shared__ float cx1[512], cy1[512], cx2[512], cy2[512], ca[512];
    int cta = blockIdx.x;              // 32
    int tid = threadIdx.x;
    int b = cta >> 3;
    int rowBase = (cta & 7) * 128;

    if (tid < 128) {
        int g = b * TOP + rowBase + tid;
        rx1[tid] = g_x1[g]; ry1[tid] = g_y1[g];
        rx2[tid] = g_x2[g]; ry2[tid] = g_y2[g];
        ra[tid] = g_area[g];
    }
    #pragma unroll
    for (int cc = 0; cc < 2; cc++) {
        __syncthreads();
        if (tid < 512) {
            int g = b * TOP + cc * 512 + tid;
            cx1[tid] = g_x1[g]; cy1[tid] = g_y1[g];
            cx2[tid] = g_x2[g]; cy2[tid] = g_y2[g];
            ca[tid] = g_area[g];
        }
        __syncthreads();
        int r = tid >> 3;
        int w = tid & 7;
        int row = rowBase + r;
        float x1 = rx1[r], y1 = ry1[r], x2 = rx2[r], y2 = ry2[r], ai = ra[r];
        u64 bits = 0;
        int cb = w * 64;
        int colBase = cc * 512 + cb;
        #pragma unroll 4
        for (int j = 0; j < 64; j++) {
            float ix = fminf(x2, cx2[cb + j]) - fmaxf(x1, cx1[cb + j]);
            float iy = fminf(y2, cy2[cb + j]) - fmaxf(y1, cy1[cb + j]);
            ix = fmaxf(ix, 0.f);
            iy = fmaxf(iy, 0.f);
            float inter = ix * iy;
            float iou = inter / (ai + ca[cb + j] - inter + 1e-6f);
            if ((colBase + j > row) & (iou > NMS_TH)) bits |= 1ull << j;
        }
        g_maskT[((size_t)b * W + (cc * 8 + w)) * M + row] = bits;
    }
}

// ---------------- kernel 6: fixpoint keep-vector + fallback + emit ----------------
__global__ void __launch_bounds__(1024) k_scan_emit(const float* __restrict__ boxes,
                                                    float* __restrict__ out) {
    extern __shared__ u64 sm[];       // 16384 u64 = 128 KB
    __shared__ u64 kw[W];
    __shared__ u64 partial[32];
    __shared__ int s_keep[POST];
    __shared__ int s_pfx[W + 1];
    __shared__ int s_changed, s_conv, s_kept, s_fail, s_i;
    int b = blockIdx.x, tid = threadIdx.x;

    for (int idx = tid; idx < M * W; idx += 1024)
        sm[idx] = g_maskT[(size_t)b * M * W + idx];
    if (tid < W) kw[tid] = ~0ull;
    if (tid == 0) { s_changed = 0; s_conv = 0; s_fail = 0; }
    __syncthreads();

    int w = tid >> 6;
    int t = tid & 63;
    const u64* mrow = sm + w * M;

    for (int iter = 0; iter < 64; iter++) {
        u64 acc = 0;
        #pragma unroll
        for (int s = 0; s < W; s++) {
            u64 kws = kw[s];
            if ((kws >> t) & 1ull) acc |= mrow[(s << 6) | t];
        }
        #pragma unroll
        for (int d = 16; d >= 1; d >>= 1) acc |= __shfl_xor_sync(0xffffffffu, acc, d);
        if ((tid & 31) == 0) partial[tid >> 5] = acc;
        __syncthreads();
        if (tid < W) {
            u64 sup = partial[2 * tid] | partial[2 * tid + 1];
            u64 nk = ~sup;
            if (nk != kw[tid]) { kw[tid] = nk; s_changed = 1; }
        }
        __syncthreads();
        bool stop = (s_changed == 0);
        __syncthreads();
        if (stop) { if (tid == 0) s_conv = 1; break; }
        if (tid == 0) s_changed = 0;
        __syncthreads();
    }
    __syncthreads();

    if (tid == 0) {
        if (!s_conv) { s_fail = 1; }
        else {
            int tot = 0;
            s_pfx[0] = 0;
            #pragma unroll
            for (int q = 0; q < W; q++) { tot += __popcll(kw[q]); s_pfx[q + 1] = tot; }
            s_fail = (tot < POST) ? 1 : 0;
            s_kept = POST;
        }
    }
    __syncthreads();

    if (!s_fail) {
        if (tid < W) {
            int pos = s_pfx[tid];
            u64 kk = kw[tid];
            for (int bit = 0; bit < 64 && pos < POST; bit++) {
                if ((kk >> bit) & 1ull) { s_keep[pos] = (tid << 6) + bit; pos++; }
            }
        }
        __syncthreads();
    } else {
        float* fx1 = (float*)sm;
        float* fy1 = fx1 + TOP;
        float* fx2 = fx1 + 2 * TOP;
        float* fy2 = fx1 + 3 * TOP;
        float* fa  = fx1 + 4 * TOP;
        unsigned char* sup = (unsigned char*)(fx1 + 5 * TOP);
        __syncthreads();
        for (int i = tid; i < TOP; i += 1024) {
            int o = b * TOP + i;
            fx1[i] = g_x1[o]; fy1[i] = g_y1[o];
            fx2[i] = g_x2[o]; fy2[i] = g_y2[o];
            fa[i] = g_area[o];
            sup[i] = 0;
        }
        __syncthreads();
        int kept = 0, cursor = 0;
        while (true) {
            if (tid == 0) {
                int i = cursor;
                while (i < TOP && sup[i]) i++;
                s_i = (i < TOP) ? i : -1;
            }
            __syncthreads();
            int i = s_i;
            if (i < 0) break;
            cursor = i + 1;
            if (tid == 0) s_keep[kept] = i;
            kept++;
            if (kept >= POST) break;
            float xi1 = fx1[i], yi1 = fy1[i], xi2 = fx2[i], yi2 = fy2[i], ai = fa[i];
            for (int j = i + 1 + tid; j < TOP; j += 1024) {
                if (!sup[j]) {
                    float ix = fminf(xi2, fx2[j]) - fmaxf(xi1, fx1[j]);
                    float iy = fminf(yi2, fy2[j]) - fmaxf(yi1, fy1[j]);
                    ix = fmaxf(ix, 0.f);
                    iy = fmaxf(iy, 0.f);
                    float inter = ix * iy;
                    if (inter / (ai + fa[j] - inter + 1e-6f) > NMS_TH) sup[j] = 1;
                }
            }
            __syncthreads();
        }
        if (tid == 0) s_kept = kept;
        __syncthreads();
    }

    int kept = s_kept;
    float* rois   = out;
    float* scores = out + B * POST * 7;
    float* labs   = out + B * POST * 7 + B * POST;
    for (int s = tid; s < POST; s += 1024) {
        int o = b * POST + s;
        if (s < kept) {
            u64 key = g_key[b * TOP + s_keep[s]];
            unsigned n = 0x7FFFu - (unsigned)((key >> 2) & 0x7FFF);
            const float* bx = boxes + ((size_t)b * N + n) * 7;
            #pragma unroll
            for (int q = 0; q < 7; q++) rois[o * 7 + q] = bx[q];
            scores[o] = __uint_as_float((unsigned)(key >> 32));
            labs[o] = (float)((key & 3ull) + 1);
        } else {
            #pragma unroll
            for (int q = 0; q < 7; q++) rois[o * 7 + q] = 0.f;
            scores[o] = 0.f;
            labs[o] = 0.f;
        }
    }
}

// ---------------- launch ----------------
extern "C" void kernel_launch(void* const* d_in, const int* in_sizes, int n_in,
                              void* d_out, int out_size) {
    const float* boxes = (const float*)d_in[0];
    const float* cls   = (const float*)d_in[1];
    if (in_sizes[0] == B * N * 3) {
        cls = (const float*)d_in[0];
        boxes = (const float*)d_in[1];
    }

    cudaFuncSetAttribute(k_sortsel, cudaFuncAttributeMaxDynamicSharedMemorySize, 65536);
    cudaFuncSetAttribute(k_scan_emit, cudaFuncAttributeMaxDynamicSharedMemorySize, 131072);

    k_hist<<<32, 1024>>>(cls);
    k_thresh<<<B, 1024>>>();
    k_compact<<<32, 1024>>>();
    k_sortsel<<<B, 1024, 65536>>>(boxes);
    k_mask<<<32, 1024>>>();
    k_scan_emit<<<B, 1024, 131072>>>(boxes, (float*)d_out);
}